// round 7
// baseline (speedup 1.0000x reference)
#include <cuda_runtime.h>
#include <math.h>

#define MAXN 10000
#define MAXE 320000

// Scratch (__device__ globals per allocation-free rule)
__device__ float g_y[MAXN * 256];     // [node]: y0[64] | y1 m-major (64+m*64+v), 1/8 folded
__device__ float g_agg[MAXN * 512];   // reference concat layout, LIN2S folded
__device__ float g_h[MAXE * 8];       // edge MLP hidden, INV_SQRT8 folded
__device__ int   g_deg[MAXN];
__device__ int   g_row[MAXN + 1];
__device__ int   g_cursor[MAXN];
__device__ int2  g_epair[MAXE];       // (src, eid) per CSR slot

#define INV_SQRT8 0.35355339059327373f
#define INV_SQRT3 0.5773502691896258f
#define LOG2F_C   0.6931471805599453f
#define LIN2S     0.015625f   // 1/(sqrt(32)*sqrt(128))
#define SCN       0.0625f     // 1/sqrt(64*4)

// ---------------------------------------------------------------------------
__global__ void zero_deg_kernel(int n) {
    int i = blockIdx.x * blockDim.x + threadIdx.x;
    if (i < n) g_deg[i] = 0;
}

__global__ void count_kernel(const int* __restrict__ eidx, int E) {
    int e = blockIdx.x * blockDim.x + threadIdx.x;
    if (e < E) atomicAdd(&g_deg[eidx[e]], 1);
}

// Single-block exclusive scan over g_deg -> g_row, g_cursor; g_row[n]=E.
__global__ void scan_kernel(int n) {
    __shared__ int part[1024];
    int tid = threadIdx.x;
    int IT = (n + 1023) >> 10;
    int base = tid * IT;
    int s = 0;
    for (int i = 0; i < IT; ++i) {
        int idx = base + i;
        if (idx < n) s += g_deg[idx];
    }
    part[tid] = s;
    __syncthreads();
    for (int off = 1; off < 1024; off <<= 1) {
        int v = (tid >= off) ? part[tid - off] : 0;
        __syncthreads();
        part[tid] += v;
        __syncthreads();
    }
    int run = part[tid] - s;
    for (int i = 0; i < IT; ++i) {
        int idx = base + i;
        if (idx < n) {
            g_row[idx] = run;
            g_cursor[idx] = run;
            run += g_deg[idx];
        }
    }
    if (tid == 1023) g_row[n] = part[1023];
}

// Fused: per-edge MLP hidden layer h + CSR scatter of (src, eid).
// MLP FMA work hides under the atomic's latency (measured: issue 42%).
__global__ void scatter_h_kernel(const int* __restrict__ eidx,
                                 const float* __restrict__ eemb,
                                 const float* __restrict__ Wfc1,
                                 int E) {
    __shared__ float sW1[64];
    int tid = threadIdx.x;
    if (tid < 64) sW1[tid] = Wfc1[tid];
    __syncthreads();
    int e = blockIdx.x * blockDim.x + tid;
    if (e >= E) return;

    int dst = __ldg(eidx + e);
    int src = __ldg(eidx + E + e);
    int pos = atomicAdd(&g_cursor[dst], 1);

    float4 e0 = __ldg((const float4*)(eemb + (size_t)e * 8));
    float4 e1 = __ldg((const float4*)(eemb + (size_t)e * 8 + 4));
    float emb[8] = {e0.x, e0.y, e0.z, e0.w, e1.x, e1.y, e1.z, e1.w};
    float h[8];
    #pragma unroll
    for (int j = 0; j < 8; ++j) {
        float z = 0.f;
        #pragma unroll
        for (int k = 0; k < 8; ++k) z = fmaf(emb[k], sW1[k * 8 + j], z);
        z *= INV_SQRT8;
        float sp = (z > 20.f) ? z : log1pf(__expf(z));
        h[j] = (sp - LOG2F_C) * INV_SQRT8;
    }
    float* o = g_h + (size_t)e * 8;
    *(float4*)o       = make_float4(h[0], h[1], h[2], h[3]);
    *(float4*)(o + 4) = make_float4(h[4], h[5], h[6], h[7]);

    g_epair[pos] = make_int2(src, e);
}

// ---------------------------------------------------------------------------
// Node pre GEMMs, K=64 (both modes in one launch).
__global__ void pre_gemm_kernel(const float* __restrict__ nf,
                                const float* __restrict__ Wl10,
                                const float* __restrict__ Wl11,
                                int n, int nb0) {
    __shared__ __align__(16) float sIn[32 * 64];
    __shared__ __align__(16) float sW[64 * 64];
    int tid = threadIdx.x;
    int v = tid & 63, rgrp = tid >> 6;
    int mode = (blockIdx.x >= nb0) ? 1 : 0;
    int blk = mode ? (blockIdx.x - nb0) : blockIdx.x;
    int rows = mode ? 3 * n : n;
    int rbase = blk * 32;
    const float* W = mode ? Wl11 : Wl10;

    for (int i = tid; i < 4096; i += 256) sW[i] = W[i];
    for (int i = tid; i < 2048; i += 256) {
        int row = i >> 6, k = i & 63;
        int rg = rbase + row;
        float val = 0.f;
        if (rg < rows) {
            if (mode == 0) val = nf[(size_t)rg * 256 + k];
            else {
                int node = rg / 3, m = rg % 3;
                val = nf[(size_t)node * 256 + 64 + k * 3 + m];
            }
        }
        sIn[i] = val;
    }
    __syncthreads();

    float acc[8] = {0.f, 0.f, 0.f, 0.f, 0.f, 0.f, 0.f, 0.f};
    for (int kk = 0; kk < 64; kk += 4) {
        float w0 = sW[(kk + 0) * 64 + v];
        float w1 = sW[(kk + 1) * 64 + v];
        float w2 = sW[(kk + 2) * 64 + v];
        float w3 = sW[(kk + 3) * 64 + v];
        #pragma unroll
        for (int r = 0; r < 8; ++r) {
            const float4 in4 = *(const float4*)(sIn + (rgrp * 8 + r) * 64 + kk);
            acc[r] = fmaf(in4.x, w0, fmaf(in4.y, w1, fmaf(in4.z, w2, fmaf(in4.w, w3, acc[r]))));
        }
    }
    #pragma unroll
    for (int r = 0; r < 8; ++r) {
        int rg = rbase + rgrp * 8 + r;
        if (rg >= rows) continue;
        float val = acc[r] * 0.125f;
        if (mode == 0) g_y[(size_t)rg * 256 + v] = val;
        else {
            int node = rg / 3, m = rg % 3;
            g_y[(size_t)node * 256 + 64 + m * 64 + v] = val;
        }
    }
}

// ---------------------------------------------------------------------------
// Aggregation (R3-proven shape): block per node, 4 groups x 64 threads,
// register weights, int2 payload, shared 4-way reduction. No atomics.
// __launch_bounds__(256,4): cap regs at 64 -> 4 blocks/SM (occ 36% -> 50%).
__global__ void __launch_bounds__(256, 4) agg_kernel(const float* __restrict__ eattr,
                           const float* __restrict__ Wfc2,
                           int E, int n) {
    __shared__ float spart[4 * 512];
    int tid = threadIdx.x;
    int u = tid & 63, grp = tid >> 6;

    // Per-thread weight columns u, 64+u, 128+u, 192+u for j=0..7 (coalesced, once).
    float wA[8], wB[8], wC[8], wD[8];
    #pragma unroll
    for (int j = 0; j < 8; ++j) {
        const float* r = Wfc2 + j * 256;
        wA[j] = __ldg(r + u);
        wB[j] = __ldg(r + 64 + u);
        wC[j] = __ldg(r + 128 + u);
        wD[j] = __ldg(r + 192 + u) * INV_SQRT3;
    }

    int node = blockIdx.x;
    int rs = g_row[node], re = g_row[node + 1];

    float a0 = 0.f, a1 = 0.f, a2 = 0.f, a3 = 0.f, a4 = 0.f, a5 = 0.f, a6 = 0.f, a7 = 0.f;

    for (int i = rs + grp; i < re; i += 4) {
        int2 cur = __ldg(g_epair + i);
        int src = cur.x, eid = cur.y;
        float4 sh = __ldg((const float4*)(eattr + (size_t)eid * 4));
        float4 h0 = __ldg((const float4*)(g_h + (size_t)eid * 8));
        float4 h1 = __ldg((const float4*)(g_h + (size_t)eid * 8 + 4));

        const float* ysrc = g_y + (size_t)src * 256;
        float xs0 = __ldg(ysrc + u);
        float x1x = __ldg(ysrc + 64 + u);
        float x1y = __ldg(ysrc + 128 + u);
        float x1z = __ldg(ysrc + 192 + u);

        float w1 = fmaf(h0.x, wA[0], fmaf(h0.y, wA[1], fmaf(h0.z, wA[2], fmaf(h0.w, wA[3],
                   fmaf(h1.x, wA[4], fmaf(h1.y, wA[5], fmaf(h1.z, wA[6], h1.w * wA[7])))))));
        float w2 = fmaf(h0.x, wB[0], fmaf(h0.y, wB[1], fmaf(h0.z, wB[2], fmaf(h0.w, wB[3],
                   fmaf(h1.x, wB[4], fmaf(h1.y, wB[5], fmaf(h1.z, wB[6], h1.w * wB[7])))))));
        float w3 = fmaf(h0.x, wC[0], fmaf(h0.y, wC[1], fmaf(h0.z, wC[2], fmaf(h0.w, wC[3],
                   fmaf(h1.x, wC[4], fmaf(h1.y, wC[5], fmaf(h1.z, wC[6], h1.w * wC[7])))))));
        float w4 = fmaf(h0.x, wD[0], fmaf(h0.y, wD[1], fmaf(h0.z, wD[2], fmaf(h0.w, wD[3],
                   fmaf(h1.x, wD[4], fmaf(h1.y, wD[5], fmaf(h1.z, wD[6], h1.w * wD[7])))))));

        float dotv = fmaf(x1x, sh.y, fmaf(x1y, sh.z, x1z * sh.w));
        float a2c = w2 * xs0;
        float a3c = w3 * sh.x;
        a0 = fmaf(w1 * xs0, sh.x, a0);
        a1 = fmaf(w4, dotv, a1);
        a2 = fmaf(a2c, sh.y, a2);
        a3 = fmaf(a2c, sh.z, a3);
        a4 = fmaf(a2c, sh.w, a4);
        a5 = fmaf(a3c, x1x, a5);
        a6 = fmaf(a3c, x1y, a6);
        a7 = fmaf(a3c, x1z, a7);
    }

    float* sp = spart + grp * 512;
    sp[u] = a0;
    sp[64 + u] = a1;
    sp[128 + 3 * u + 0] = a2;
    sp[128 + 3 * u + 1] = a3;
    sp[128 + 3 * u + 2] = a4;
    sp[320 + 3 * u + 0] = a5;
    sp[320 + 3 * u + 1] = a6;
    sp[320 + 3 * u + 2] = a7;
    __syncthreads();

    float* arow = g_agg + (size_t)node * 512;
    for (int idx = tid; idx < 512; idx += 256)
        arow[idx] = (spart[idx] + spart[512 + idx] + spart[1024 + idx] + spart[1536 + idx]) * LIN2S;
}

// ---------------------------------------------------------------------------
// Node post GEMM, K=384 (3 chunks of 128): [agg_part | attrs (x) x] @ [W_lin2 ; W_sc].
__global__ void post_gemm_kernel(const float* __restrict__ nf,
                                 const float* __restrict__ attrs,
                                 const float* __restrict__ Wl20,
                                 const float* __restrict__ Wl21,
                                 const float* __restrict__ Wsc0,
                                 const float* __restrict__ Wsc1,
                                 float* __restrict__ out,
                                 int n, int nb0) {
    __shared__ __align__(16) float sIn[32 * 128];   // 16 KB
    __shared__ __align__(16) float sW[128 * 64];    // 32 KB
    int tid = threadIdx.x;
    int v = tid & 63, rgrp = tid >> 6;
    int mode = (blockIdx.x >= nb0) ? 1 : 0;
    int blk = mode ? (blockIdx.x - nb0) : blockIdx.x;
    int rows = mode ? 3 * n : n;
    int rbase = blk * 32;
    const float* Wlin = mode ? Wl21 : Wl20;
    const float* Wsc  = mode ? Wsc1 : Wsc0;

    float acc[8] = {0.f, 0.f, 0.f, 0.f, 0.f, 0.f, 0.f, 0.f};

    for (int c = 0; c < 3; ++c) {
        for (int i = tid; i < 8192; i += 256) {
            int kk = i >> 6, vv = i & 63;
            int k = c * 128 + kk;
            float w;
            if (k < 128) w = Wlin[k * 64 + vv];
            else {
                int t2 = k - 128, a = t2 >> 6, uu = t2 & 63;
                w = Wsc[uu * 256 + a * 64 + vv];
            }
            sW[i] = w;
        }
        for (int i = tid; i < 4096; i += 256) {
            int row = i >> 7, kk = i & 127;
            int rg = rbase + row;
            int k = c * 128 + kk;
            float val = 0.f;
            if (rg < rows) {
                if (mode == 0) {
                    if (k < 128) val = g_agg[(size_t)rg * 512 + k];
                    else {
                        int t2 = k - 128, a = t2 >> 6, uu = t2 & 63;
                        val = attrs[(size_t)rg * 4 + a] * nf[(size_t)rg * 256 + uu] * SCN;
                    }
                } else {
                    int node = rg / 3, m = rg % 3;
                    if (k < 128) val = g_agg[(size_t)node * 512 + 128 + k * 3 + m];
                    else {
                        int t2 = k - 128, a = t2 >> 6, uu = t2 & 63;
                        val = attrs[(size_t)node * 4 + a] * nf[(size_t)node * 256 + 64 + uu * 3 + m] * SCN;
                    }
                }
            }
            sIn[i] = val;
        }
        __syncthreads();

        for (int kk = 0; kk < 128; kk += 4) {
            float w0 = sW[(kk + 0) * 64 + v];
            float w1 = sW[(kk + 1) * 64 + v];
            float w2 = sW[(kk + 2) * 64 + v];
            float w3 = sW[(kk + 3) * 64 + v];
            #pragma unroll
            for (int r = 0; r < 8; ++r) {
                const float4 in4 = *(const float4*)(sIn + (rgrp * 8 + r) * 128 + kk);
                acc[r] = fmaf(in4.x, w0, fmaf(in4.y, w1, fmaf(in4.z, w2, fmaf(in4.w, w3, acc[r]))));
            }
        }
        __syncthreads();
    }

    #pragma unroll
    for (int r = 0; r < 8; ++r) {
        int rg = rbase + rgrp * 8 + r;
        if (rg >= rows) continue;
        if (mode == 0) out[(size_t)rg * 256 + v] = acc[r];
        else {
            int node = rg / 3, m = rg % 3;
            out[(size_t)node * 256 + 64 + v * 3 + m] = acc[r];
        }
    }
}

// ---------------------------------------------------------------------------
extern "C" void kernel_launch(void* const* d_in, const int* in_sizes, int n_in,
                              void* d_out, int out_size) {
    const float* nf    = (const float*)d_in[0];
    const float* attrs = (const float*)d_in[1];
    const float* ea    = (const float*)d_in[2];
    const float* ee    = (const float*)d_in[3];
    const int*   ei    = (const int*)d_in[4];
    const float* Wl10  = (const float*)d_in[5];
    const float* Wl11  = (const float*)d_in[6];
    const float* Wfc1  = (const float*)d_in[7];
    const float* Wfc2  = (const float*)d_in[8];
    const float* Wl20  = (const float*)d_in[9];
    const float* Wl21  = (const float*)d_in[10];
    const float* Wsc0  = (const float*)d_in[11];
    const float* Wsc1  = (const float*)d_in[12];
    float* out = (float*)d_out;

    int n = in_sizes[0] / 256;
    int E = in_sizes[2] / 4;

    // CSR build (compact g_epair) + edge MLP fused into scatter
    zero_deg_kernel<<<(n + 255) / 256, 256>>>(n);
    count_kernel<<<(E + 255) / 256, 256>>>(ei, E);
    scan_kernel<<<1, 1024>>>(n);
    scatter_h_kernel<<<(E + 255) / 256, 256>>>(ei, ee, Wfc1, E);

    // Node pre (y0, y1) fused
    int pre_nb0 = (n + 31) / 32, pre_nb1 = (3 * n + 31) / 32;
    pre_gemm_kernel<<<pre_nb0 + pre_nb1, 256>>>(nf, Wl10, Wl11, n, pre_nb0);

    // Aggregation (block-per-node, 4 blocks/SM)
    agg_kernel<<<n, 256>>>(ea, Wfc2, E, n);

    // Node post (o0, o1) fused
    int post_nb0 = (n + 31) / 32, post_nb1 = (3 * n + 31) / 32;
    post_gemm_kernel<<<post_nb0 + post_nb1, 256>>>(nf, attrs, Wl20, Wl21, Wsc0, Wsc1, out, n, post_nb0);
}

// round 8
// speedup vs baseline: 1.6640x; 1.6640x over previous
#include <cuda_runtime.h>
#include <math.h>

#define MAXN 10000
#define MAXE 320000

// Scratch (__device__ globals per allocation-free rule)
__device__ float g_y[MAXN * 256];     // [node]: y0[64] | y1 m-major (64+m*64+v), scale 1/8 folded
__device__ float g_agg[MAXN * 512];   // reference concat layout, LIN2S (1/64) folded
__device__ float g_h[MAXE * 8];       // edge MLP hidden, INV_SQRT8 (2nd layer scale) folded
__device__ int   g_deg[MAXN];
__device__ int   g_row[MAXN + 1];
__device__ int   g_cursor[MAXN];
__device__ int   g_elist[MAXE];

#define INV_SQRT8 0.35355339059327373f
#define INV_SQRT3 0.5773502691896258f
#define LOG2F_C   0.6931471805599453f
#define LIN2S     0.015625f   // 1/(sqrt(32)*sqrt(128))
#define SCN       0.0625f     // 1/sqrt(64*4)

// ---------------------------------------------------------------------------
__global__ void zero_deg_kernel(int n) {
    int i = blockIdx.x * blockDim.x + threadIdx.x;
    if (i < n) g_deg[i] = 0;
}

__global__ void count_kernel(const int* __restrict__ eidx, int E) {
    int e = blockIdx.x * blockDim.x + threadIdx.x;
    if (e < E) atomicAdd(&g_deg[eidx[e]], 1);
}

// Single-block exclusive scan over g_deg -> g_row, g_cursor; g_row[n]=E.
__global__ void scan_kernel(int n) {
    __shared__ int part[1024];
    int tid = threadIdx.x;
    int IT = (n + 1023) >> 10;
    int base = tid * IT;
    int s = 0;
    for (int i = 0; i < IT; ++i) {
        int idx = base + i;
        if (idx < n) s += g_deg[idx];
    }
    part[tid] = s;
    __syncthreads();
    // Hillis-Steele inclusive scan
    for (int off = 1; off < 1024; off <<= 1) {
        int v = (tid >= off) ? part[tid - off] : 0;
        __syncthreads();
        part[tid] += v;
        __syncthreads();
    }
    int run = part[tid] - s;  // exclusive prefix for this thread's range
    for (int i = 0; i < IT; ++i) {
        int idx = base + i;
        if (idx < n) {
            g_row[idx] = run;
            g_cursor[idx] = run;
            run += g_deg[idx];
        }
    }
    if (tid == 1023) g_row[n] = part[1023];
}

// Fused: per-edge MLP hidden layer h + CSR scatter (single change vs R3 baseline).
__global__ void scatter_h_kernel(const int* __restrict__ eidx,
                                 const float* __restrict__ eemb,
                                 const float* __restrict__ Wfc1,
                                 int E) {
    __shared__ float sW1[64];
    int tid = threadIdx.x;
    if (tid < 64) sW1[tid] = Wfc1[tid];
    __syncthreads();
    int e = blockIdx.x * blockDim.x + tid;
    if (e >= E) return;

    // Kick off the atomic early; compute h underneath its latency.
    int dst = __ldg(eidx + e);
    int pos = atomicAdd(&g_cursor[dst], 1);

    float4 e0 = *(const float4*)(eemb + (size_t)e * 8);
    float4 e1 = *(const float4*)(eemb + (size_t)e * 8 + 4);
    float emb[8] = {e0.x, e0.y, e0.z, e0.w, e1.x, e1.y, e1.z, e1.w};
    float h[8];
    #pragma unroll
    for (int j = 0; j < 8; ++j) {
        float z = 0.f;
        #pragma unroll
        for (int k = 0; k < 8; ++k) z = fmaf(emb[k], sW1[k * 8 + j], z);
        z *= INV_SQRT8;
        float sp = (z > 20.f) ? z : log1pf(__expf(z));
        h[j] = (sp - LOG2F_C) * INV_SQRT8;
    }
    float* o = g_h + (size_t)e * 8;
    *(float4*)o       = make_float4(h[0], h[1], h[2], h[3]);
    *(float4*)(o + 4) = make_float4(h[4], h[5], h[6], h[7]);

    g_elist[pos] = e;
}

// ---------------------------------------------------------------------------
// Node pre GEMMs, K=64 (both modes in one launch).
__global__ void pre_gemm_kernel(const float* __restrict__ nf,
                                const float* __restrict__ Wl10,
                                const float* __restrict__ Wl11,
                                int n, int nb0) {
    __shared__ __align__(16) float sIn[32 * 64];
    __shared__ __align__(16) float sW[64 * 64];
    int tid = threadIdx.x;
    int v = tid & 63, rgrp = tid >> 6;
    int mode = (blockIdx.x >= nb0) ? 1 : 0;
    int blk = mode ? (blockIdx.x - nb0) : blockIdx.x;
    int rows = mode ? 3 * n : n;
    int rbase = blk * 32;
    const float* W = mode ? Wl11 : Wl10;

    for (int i = tid; i < 4096; i += 256) sW[i] = W[i];
    for (int i = tid; i < 2048; i += 256) {
        int row = i >> 6, k = i & 63;
        int rg = rbase + row;
        float val = 0.f;
        if (rg < rows) {
            if (mode == 0) val = nf[(size_t)rg * 256 + k];
            else {
                int node = rg / 3, m = rg % 3;
                val = nf[(size_t)node * 256 + 64 + k * 3 + m];
            }
        }
        sIn[i] = val;
    }
    __syncthreads();

    float acc[8] = {0.f, 0.f, 0.f, 0.f, 0.f, 0.f, 0.f, 0.f};
    for (int kk = 0; kk < 64; kk += 4) {
        float w0 = sW[(kk + 0) * 64 + v];
        float w1 = sW[(kk + 1) * 64 + v];
        float w2 = sW[(kk + 2) * 64 + v];
        float w3 = sW[(kk + 3) * 64 + v];
        #pragma unroll
        for (int r = 0; r < 8; ++r) {
            const float4 in4 = *(const float4*)(sIn + (rgrp * 8 + r) * 64 + kk);
            acc[r] = fmaf(in4.x, w0, fmaf(in4.y, w1, fmaf(in4.z, w2, fmaf(in4.w, w3, acc[r]))));
        }
    }
    #pragma unroll
    for (int r = 0; r < 8; ++r) {
        int rg = rbase + rgrp * 8 + r;
        if (rg >= rows) continue;
        float val = acc[r] * 0.125f;
        if (mode == 0) g_y[(size_t)rg * 256 + v] = val;
        else {
            int node = rg / 3, m = rg % 3;
            g_y[(size_t)node * 256 + 64 + m * 64 + v] = val;
        }
    }
}

// ---------------------------------------------------------------------------
// Aggregation (exact R3 shape): block per node, 4 groups x 64 threads,
// register-resident W_fc2 columns, shared 4-way reduction. No atomics.
__global__ void __launch_bounds__(256) agg_kernel(const float* __restrict__ eattr,
                           const int*   __restrict__ eidx,
                           const float* __restrict__ Wfc2,
                           int E, int n) {
    __shared__ float spart[4 * 512];
    int tid = threadIdx.x;
    int u = tid & 63, grp = tid >> 6;

    // Per-thread weight columns u, 64+u, 128+u, 192+u for j=0..7 (coalesced loads, once).
    float wA[8], wB[8], wC[8], wD[8];
    #pragma unroll
    for (int j = 0; j < 8; ++j) {
        const float* r = Wfc2 + j * 256;
        wA[j] = __ldg(r + u);
        wB[j] = __ldg(r + 64 + u);
        wC[j] = __ldg(r + 128 + u);
        wD[j] = __ldg(r + 192 + u);
    }

    int node = blockIdx.x;
    int rs = g_row[node], re = g_row[node + 1];

    float a0 = 0.f, a1 = 0.f, a2 = 0.f, a3 = 0.f, a4 = 0.f, a5 = 0.f, a6 = 0.f, a7 = 0.f;

    for (int i = rs + grp; i < re; i += 4) {
        int eid = __ldg(g_elist + i);
        int src = __ldg(eidx + E + eid);
        float4 sh = __ldg((const float4*)(eattr + (size_t)eid * 4));
        float4 h0 = __ldg((const float4*)(g_h + (size_t)eid * 8));
        float4 h1 = __ldg((const float4*)(g_h + (size_t)eid * 8 + 4));

        const float* ysrc = g_y + (size_t)src * 256;
        float xs0 = __ldg(ysrc + u);
        float x1x = __ldg(ysrc + 64 + u);
        float x1y = __ldg(ysrc + 128 + u);
        float x1z = __ldg(ysrc + 192 + u);

        float w1 = fmaf(h0.x, wA[0], fmaf(h0.y, wA[1], fmaf(h0.z, wA[2], fmaf(h0.w, wA[3],
                   fmaf(h1.x, wA[4], fmaf(h1.y, wA[5], fmaf(h1.z, wA[6], h1.w * wA[7])))))));
        float w2 = fmaf(h0.x, wB[0], fmaf(h0.y, wB[1], fmaf(h0.z, wB[2], fmaf(h0.w, wB[3],
                   fmaf(h1.x, wB[4], fmaf(h1.y, wB[5], fmaf(h1.z, wB[6], h1.w * wB[7])))))));
        float w3 = fmaf(h0.x, wC[0], fmaf(h0.y, wC[1], fmaf(h0.z, wC[2], fmaf(h0.w, wC[3],
                   fmaf(h1.x, wC[4], fmaf(h1.y, wC[5], fmaf(h1.z, wC[6], h1.w * wC[7])))))));
        float w4 = fmaf(h0.x, wD[0], fmaf(h0.y, wD[1], fmaf(h0.z, wD[2], fmaf(h0.w, wD[3],
                   fmaf(h1.x, wD[4], fmaf(h1.y, wD[5], fmaf(h1.z, wD[6], h1.w * wD[7])))))));

        float dotv = fmaf(x1x, sh.y, fmaf(x1y, sh.z, x1z * sh.w));
        float a2c = w2 * xs0;
        float a3c = w3 * sh.x;
        a0 = fmaf(w1 * xs0, sh.x, a0);
        a1 = fmaf(w4 * INV_SQRT3, dotv, a1);
        a2 = fmaf(a2c, sh.y, a2);
        a3 = fmaf(a2c, sh.z, a3);
        a4 = fmaf(a2c, sh.w, a4);
        a5 = fmaf(a3c, x1x, a5);
        a6 = fmaf(a3c, x1y, a6);
        a7 = fmaf(a3c, x1z, a7);
    }

    float* sp = spart + grp * 512;
    sp[u] = a0;
    sp[64 + u] = a1;
    sp[128 + 3 * u + 0] = a2;
    sp[128 + 3 * u + 1] = a3;
    sp[128 + 3 * u + 2] = a4;
    sp[320 + 3 * u + 0] = a5;
    sp[320 + 3 * u + 1] = a6;
    sp[320 + 3 * u + 2] = a7;
    __syncthreads();

    float* arow = g_agg + (size_t)node * 512;
    for (int idx = tid; idx < 512; idx += 256)
        arow[idx] = (spart[idx] + spart[512 + idx] + spart[1024 + idx] + spart[1536 + idx]) * LIN2S;
}

// ---------------------------------------------------------------------------
// Node post GEMM, K=384 (3 chunks of 128): [agg_part | attrs (x) x] @ [W_lin2 ; W_sc].
__global__ void post_gemm_kernel(const float* __restrict__ nf,
                                 const float* __restrict__ attrs,
                                 const float* __restrict__ Wl20,
                                 const float* __restrict__ Wl21,
                                 const float* __restrict__ Wsc0,
                                 const float* __restrict__ Wsc1,
                                 float* __restrict__ out,
                                 int n, int nb0) {
    __shared__ __align__(16) float sIn[32 * 128];   // 16 KB
    __shared__ __align__(16) float sW[128 * 64];    // 32 KB
    int tid = threadIdx.x;
    int v = tid & 63, rgrp = tid >> 6;
    int mode = (blockIdx.x >= nb0) ? 1 : 0;
    int blk = mode ? (blockIdx.x - nb0) : blockIdx.x;
    int rows = mode ? 3 * n : n;
    int rbase = blk * 32;
    const float* Wlin = mode ? Wl21 : Wl20;
    const float* Wsc  = mode ? Wsc1 : Wsc0;

    float acc[8] = {0.f, 0.f, 0.f, 0.f, 0.f, 0.f, 0.f, 0.f};

    for (int c = 0; c < 3; ++c) {
        for (int i = tid; i < 8192; i += 256) {
            int kk = i >> 6, vv = i & 63;
            int k = c * 128 + kk;
            float w;
            if (k < 128) w = Wlin[k * 64 + vv];
            else {
                int t2 = k - 128, a = t2 >> 6, uu = t2 & 63;
                w = Wsc[uu * 256 + a * 64 + vv];
            }
            sW[i] = w;
        }
        for (int i = tid; i < 4096; i += 256) {
            int row = i >> 7, kk = i & 127;
            int rg = rbase + row;
            int k = c * 128 + kk;
            float val = 0.f;
            if (rg < rows) {
                if (mode == 0) {
                    if (k < 128) val = g_agg[(size_t)rg * 512 + k];
                    else {
                        int t2 = k - 128, a = t2 >> 6, uu = t2 & 63;
                        val = attrs[(size_t)rg * 4 + a] * nf[(size_t)rg * 256 + uu] * SCN;
                    }
                } else {
                    int node = rg / 3, m = rg % 3;
                    if (k < 128) val = g_agg[(size_t)node * 512 + 128 + k * 3 + m];
                    else {
                        int t2 = k - 128, a = t2 >> 6, uu = t2 & 63;
                        val = attrs[(size_t)node * 4 + a] * nf[(size_t)node * 256 + 64 + uu * 3 + m] * SCN;
                    }
                }
            }
            sIn[i] = val;
        }
        __syncthreads();

        for (int kk = 0; kk < 128; kk += 4) {
            float w0 = sW[(kk + 0) * 64 + v];
            float w1 = sW[(kk + 1) * 64 + v];
            float w2 = sW[(kk + 2) * 64 + v];
            float w3 = sW[(kk + 3) * 64 + v];
            #pragma unroll
            for (int r = 0; r < 8; ++r) {
                const float4 in4 = *(const float4*)(sIn + (rgrp * 8 + r) * 128 + kk);
                acc[r] = fmaf(in4.x, w0, fmaf(in4.y, w1, fmaf(in4.z, w2, fmaf(in4.w, w3, acc[r]))));
            }
        }
        __syncthreads();
    }

    #pragma unroll
    for (int r = 0; r < 8; ++r) {
        int rg = rbase + rgrp * 8 + r;
        if (rg >= rows) continue;
        if (mode == 0) out[(size_t)rg * 256 + v] = acc[r];
        else {
            int node = rg / 3, m = rg % 3;
            out[(size_t)node * 256 + 64 + v * 3 + m] = acc[r];
        }
    }
}

// ---------------------------------------------------------------------------
extern "C" void kernel_launch(void* const* d_in, const int* in_sizes, int n_in,
                              void* d_out, int out_size) {
    const float* nf    = (const float*)d_in[0];
    const float* attrs = (const float*)d_in[1];
    const float* ea    = (const float*)d_in[2];
    const float* ee    = (const float*)d_in[3];
    const int*   ei    = (const int*)d_in[4];
    const float* Wl10  = (const float*)d_in[5];
    const float* Wl11  = (const float*)d_in[6];
    const float* Wfc1  = (const float*)d_in[7];
    const float* Wfc2  = (const float*)d_in[8];
    const float* Wl20  = (const float*)d_in[9];
    const float* Wl21  = (const float*)d_in[10];
    const float* Wsc0  = (const float*)d_in[11];
    const float* Wsc1  = (const float*)d_in[12];
    float* out = (float*)d_out;

    int n = in_sizes[0] / 256;
    int E = in_sizes[2] / 4;

    // CSR build; h fused into scatter (the ONLY change vs the 270.4us baseline)
    zero_deg_kernel<<<(n + 255) / 256, 256>>>(n);
    count_kernel<<<(E + 255) / 256, 256>>>(ei, E);
    scan_kernel<<<1, 1024>>>(n);
    scatter_h_kernel<<<(E + 255) / 256, 256>>>(ei, ee, Wfc1, E);

    // Node pre (y0, y1)
    int pre_nb0 = (n + 31) / 32, pre_nb1 = (3 * n + 31) / 32;
    pre_gemm_kernel<<<pre_nb0 + pre_nb1, 256>>>(nf, Wl10, Wl11, n, pre_nb0);

    // Aggregation (no atomics, register weights)
    agg_kernel<<<n, 256>>>(ea, ei, Wfc2, E, n);

    // Node post (o0, o1)
    int post_nb0 = (n + 31) / 32, post_nb1 = (3 * n + 31) / 32;
    post_gemm_kernel<<<post_nb0 + post_nb1, 256>>>(nf, attrs, Wl20, Wl21, Wsc0, Wsc1, out, n, post_nb0);
}

// round 11
// speedup vs baseline: 1.6812x; 1.0104x over previous
#include <cuda_runtime.h>
#include <math.h>

#define MAXN 10000
#define MAXE 320000

// Scratch (__device__ globals per allocation-free rule)
__device__ float  g_y[MAXN * 256];    // [node]: y0[64] | y1 m-major (64+m*64+v), scale 1/8 folded
__device__ float  g_agg[MAXN * 512];  // reference concat layout, LIN2S (1/64) folded
__device__ float4 g_erec[MAXE * 4];   // packed CSR edge record: [sh | h0..3 | h4..7 | src,pad]
__device__ int    g_deg[MAXN];
__device__ int    g_row[MAXN + 1];
__device__ int    g_cursor[MAXN];

#define INV_SQRT8 0.35355339059327373f
#define INV_SQRT3 0.5773502691896258f
#define LOG2F_C   0.6931471805599453f
#define LIN2S     0.015625f   // 1/(sqrt(32)*sqrt(128))
#define SCN       0.0625f     // 1/sqrt(64*4)

// ---------------------------------------------------------------------------
__global__ void zero_deg_kernel(int n) {
    int i = blockIdx.x * blockDim.x + threadIdx.x;
    if (i < n) g_deg[i] = 0;
}

__global__ void count_kernel(const int* __restrict__ eidx, int E) {
    int e = blockIdx.x * blockDim.x + threadIdx.x;
    if (e < E) atomicAdd(&g_deg[eidx[e]], 1);
}

// Single-block exclusive scan over g_deg -> g_row, g_cursor; g_row[n]=E.
__global__ void scan_kernel(int n) {
    __shared__ int part[1024];
    int tid = threadIdx.x;
    int IT = (n + 1023) >> 10;
    int base = tid * IT;
    int s = 0;
    for (int i = 0; i < IT; ++i) {
        int idx = base + i;
        if (idx < n) s += g_deg[idx];
    }
    part[tid] = s;
    __syncthreads();
    // Hillis-Steele inclusive scan
    for (int off = 1; off < 1024; off <<= 1) {
        int v = (tid >= off) ? part[tid - off] : 0;
        __syncthreads();
        part[tid] += v;
        __syncthreads();
    }
    int run = part[tid] - s;  // exclusive prefix for this thread's range
    for (int i = 0; i < IT; ++i) {
        int idx = base + i;
        if (idx < n) {
            g_row[idx] = run;
            g_cursor[idx] = run;
            run += g_deg[idx];
        }
    }
    if (tid == 1023) g_row[n] = part[1023];
}

// Fused: per-edge MLP hidden layer h + CSR scatter of the PACKED 64B record
// (sh[4], h[8], src). Agg then reads node-sequential cache lines.
__global__ void scatter_h_kernel(const int* __restrict__ eidx,
                                 const float* __restrict__ eemb,
                                 const float* __restrict__ eattr,
                                 const float* __restrict__ Wfc1,
                                 int E) {
    __shared__ float sW1[64];
    int tid = threadIdx.x;
    if (tid < 64) sW1[tid] = Wfc1[tid];
    __syncthreads();
    int e = blockIdx.x * blockDim.x + tid;
    if (e >= E) return;

    // Kick off the atomic early; compute h underneath its latency.
    int dst = __ldg(eidx + e);
    int src = __ldg(eidx + E + e);
    int pos = atomicAdd(&g_cursor[dst], 1);

    float4 sh = __ldg((const float4*)(eattr + (size_t)e * 4));
    float4 e0 = *(const float4*)(eemb + (size_t)e * 8);
    float4 e1 = *(const float4*)(eemb + (size_t)e * 8 + 4);
    float emb[8] = {e0.x, e0.y, e0.z, e0.w, e1.x, e1.y, e1.z, e1.w};
    float h[8];
    #pragma unroll
    for (int j = 0; j < 8; ++j) {
        float z = 0.f;
        #pragma unroll
        for (int k = 0; k < 8; ++k) z = fmaf(emb[k], sW1[k * 8 + j], z);
        z *= INV_SQRT8;
        float sp = (z > 20.f) ? z : log1pf(__expf(z));
        h[j] = (sp - LOG2F_C) * INV_SQRT8;
    }

    float4* rp = g_erec + (size_t)pos * 4;
    rp[0] = sh;
    rp[1] = make_float4(h[0], h[1], h[2], h[3]);
    rp[2] = make_float4(h[4], h[5], h[6], h[7]);
    rp[3] = make_float4(__int_as_float(src), 0.f, 0.f, 0.f);
}

// ---------------------------------------------------------------------------
// Node pre GEMMs, K=64 (both modes in one launch).
__global__ void pre_gemm_kernel(const float* __restrict__ nf,
                                const float* __restrict__ Wl10,
                                const float* __restrict__ Wl11,
                                int n, int nb0) {
    __shared__ __align__(16) float sIn[32 * 64];
    __shared__ __align__(16) float sW[64 * 64];
    int tid = threadIdx.x;
    int v = tid & 63, rgrp = tid >> 6;
    int mode = (blockIdx.x >= nb0) ? 1 : 0;
    int blk = mode ? (blockIdx.x - nb0) : blockIdx.x;
    int rows = mode ? 3 * n : n;
    int rbase = blk * 32;
    const float* W = mode ? Wl11 : Wl10;

    for (int i = tid; i < 4096; i += 256) sW[i] = W[i];
    for (int i = tid; i < 2048; i += 256) {
        int row = i >> 6, k = i & 63;
        int rg = rbase + row;
        float val = 0.f;
        if (rg < rows) {
            if (mode == 0) val = nf[(size_t)rg * 256 + k];
            else {
                int node = rg / 3, m = rg % 3;
                val = nf[(size_t)node * 256 + 64 + k * 3 + m];
            }
        }
        sIn[i] = val;
    }
    __syncthreads();

    float acc[8] = {0.f, 0.f, 0.f, 0.f, 0.f, 0.f, 0.f, 0.f};
    for (int kk = 0; kk < 64; kk += 4) {
        float w0 = sW[(kk + 0) * 64 + v];
        float w1 = sW[(kk + 1) * 64 + v];
        float w2 = sW[(kk + 2) * 64 + v];
        float w3 = sW[(kk + 3) * 64 + v];
        #pragma unroll
        for (int r = 0; r < 8; ++r) {
            const float4 in4 = *(const float4*)(sIn + (rgrp * 8 + r) * 64 + kk);
            acc[r] = fmaf(in4.x, w0, fmaf(in4.y, w1, fmaf(in4.z, w2, fmaf(in4.w, w3, acc[r]))));
        }
    }
    #pragma unroll
    for (int r = 0; r < 8; ++r) {
        int rg = rbase + rgrp * 8 + r;
        if (rg >= rows) continue;
        float val = acc[r] * 0.125f;
        if (mode == 0) g_y[(size_t)rg * 256 + v] = val;
        else {
            int node = rg / 3, m = rg % 3;
            g_y[(size_t)node * 256 + 64 + m * 64 + v] = val;
        }
    }
}

// ---------------------------------------------------------------------------
// Aggregation: block per node, 4 groups x 64 threads, register weights,
// packed-record stream (node-sequential), shared 4-way reduction. No atomics.
__global__ void __launch_bounds__(256) agg_kernel(const float* __restrict__ Wfc2,
                           int E, int n) {
    __shared__ float spart[4 * 512];
    int tid = threadIdx.x;
    int u = tid & 63, grp = tid >> 6;

    // Per-thread weight columns u, 64+u, 128+u, 192+u for j=0..7 (coalesced loads, once).
    float wA[8], wB[8], wC[8], wD[8];
    #pragma unroll
    for (int j = 0; j < 8; ++j) {
        const float* r = Wfc2 + j * 256;
        wA[j] = __ldg(r + u);
        wB[j] = __ldg(r + 64 + u);
        wC[j] = __ldg(r + 128 + u);
        wD[j] = __ldg(r + 192 + u);
    }

    int node = blockIdx.x;
    int rs = g_row[node], re = g_row[node + 1];

    float a0 = 0.f, a1 = 0.f, a2 = 0.f, a3 = 0.f, a4 = 0.f, a5 = 0.f, a6 = 0.f, a7 = 0.f;

    for (int i = rs + grp; i < re; i += 4) {
        const float4* rp = g_erec + (size_t)i * 4;   // sequential per node, uniform per group
        float4 sh = __ldg(rp);
        float4 h0 = __ldg(rp + 1);
        float4 h1 = __ldg(rp + 2);
        int src = __float_as_int(__ldg((const float*)(rp + 3)));

        const float* ysrc = g_y + (size_t)src * 256;
        float xs0 = __ldg(ysrc + u);
        float x1x = __ldg(ysrc + 64 + u);
        float x1y = __ldg(ysrc + 128 + u);
        float x1z = __ldg(ysrc + 192 + u);

        float w1 = fmaf(h0.x, wA[0], fmaf(h0.y, wA[1], fmaf(h0.z, wA[2], fmaf(h0.w, wA[3],
                   fmaf(h1.x, wA[4], fmaf(h1.y, wA[5], fmaf(h1.z, wA[6], h1.w * wA[7])))))));
        float w2 = fmaf(h0.x, wB[0], fmaf(h0.y, wB[1], fmaf(h0.z, wB[2], fmaf(h0.w, wB[3],
                   fmaf(h1.x, wB[4], fmaf(h1.y, wB[5], fmaf(h1.z, wB[6], h1.w * wB[7])))))));
        float w3 = fmaf(h0.x, wC[0], fmaf(h0.y, wC[1], fmaf(h0.z, wC[2], fmaf(h0.w, wC[3],
                   fmaf(h1.x, wC[4], fmaf(h1.y, wC[5], fmaf(h1.z, wC[6], h1.w * wC[7])))))));
        float w4 = fmaf(h0.x, wD[0], fmaf(h0.y, wD[1], fmaf(h0.z, wD[2], fmaf(h0.w, wD[3],
                   fmaf(h1.x, wD[4], fmaf(h1.y, wD[5], fmaf(h1.z, wD[6], h1.w * wD[7])))))));

        float dotv = fmaf(x1x, sh.y, fmaf(x1y, sh.z, x1z * sh.w));
        float a2c = w2 * xs0;
        float a3c = w3 * sh.x;
        a0 = fmaf(w1 * xs0, sh.x, a0);
        a1 = fmaf(w4 * INV_SQRT3, dotv, a1);
        a2 = fmaf(a2c, sh.y, a2);
        a3 = fmaf(a2c, sh.z, a3);
        a4 = fmaf(a2c, sh.w, a4);
        a5 = fmaf(a3c, x1x, a5);
        a6 = fmaf(a3c, x1y, a6);
        a7 = fmaf(a3c, x1z, a7);
    }

    float* sp = spart + grp * 512;
    sp[u] = a0;
    sp[64 + u] = a1;
    sp[128 + 3 * u + 0] = a2;
    sp[128 + 3 * u + 1] = a3;
    sp[128 + 3 * u + 2] = a4;
    sp[320 + 3 * u + 0] = a5;
    sp[320 + 3 * u + 1] = a6;
    sp[320 + 3 * u + 2] = a7;
    __syncthreads();

    float* arow = g_agg + (size_t)node * 512;
    for (int idx = tid; idx < 512; idx += 256)
        arow[idx] = (spart[idx] + spart[512 + idx] + spart[1024 + idx] + spart[1536 + idx]) * LIN2S;
}

// ---------------------------------------------------------------------------
// Node post GEMM, K=384 (3 chunks of 128): [agg_part | attrs (x) x] @ [W_lin2 ; W_sc].
__global__ void post_gemm_kernel(const float* __restrict__ nf,
                                 const float* __restrict__ attrs,
                                 const float* __restrict__ Wl20,
                                 const float* __restrict__ Wl21,
                                 const float* __restrict__ Wsc0,
                                 const float* __restrict__ Wsc1,
                                 float* __restrict__ out,
                                 int n, int nb0) {
    __shared__ __align__(16) float sIn[32 * 128];   // 16 KB
    __shared__ __align__(16) float sW[128 * 64];    // 32 KB
    int tid = threadIdx.x;
    int v = tid & 63, rgrp = tid >> 6;
    int mode = (blockIdx.x >= nb0) ? 1 : 0;
    int blk = mode ? (blockIdx.x - nb0) : blockIdx.x;
    int rows = mode ? 3 * n : n;
    int rbase = blk * 32;
    const float* Wlin = mode ? Wl21 : Wl20;
    const float* Wsc  = mode ? Wsc1 : Wsc0;

    float acc[8] = {0.f, 0.f, 0.f, 0.f, 0.f, 0.f, 0.f, 0.f};

    for (int c = 0; c < 3; ++c) {
        for (int i = tid; i < 8192; i += 256) {
            int kk = i >> 6, vv = i & 63;
            int k = c * 128 + kk;
            float w;
            if (k < 128) w = Wlin[k * 64 + vv];
            else {
                int t2 = k - 128, a = t2 >> 6, uu = t2 & 63;
                w = Wsc[uu * 256 + a * 64 + vv];
            }
            sW[i] = w;
        }
        for (int i = tid; i < 4096; i += 256) {
            int row = i >> 7, kk = i & 127;
            int rg = rbase + row;
            int k = c * 128 + kk;
            float val = 0.f;
            if (rg < rows) {
                if (mode == 0) {
                    if (k < 128) val = g_agg[(size_t)rg * 512 + k];
                    else {
                        int t2 = k - 128, a = t2 >> 6, uu = t2 & 63;
                        val = attrs[(size_t)rg * 4 + a] * nf[(size_t)rg * 256 + uu] * SCN;
                    }
                } else {
                    int node = rg / 3, m = rg % 3;
                    if (k < 128) val = g_agg[(size_t)node * 512 + 128 + k * 3 + m];
                    else {
                        int t2 = k - 128, a = t2 >> 6, uu = t2 & 63;
                        val = attrs[(size_t)node * 4 + a] * nf[(size_t)node * 256 + 64 + uu * 3 + m] * SCN;
                    }
                }
            }
            sIn[i] = val;
        }
        __syncthreads();

        for (int kk = 0; kk < 128; kk += 4) {
            float w0 = sW[(kk + 0) * 64 + v];
            float w1 = sW[(kk + 1) * 64 + v];
            float w2 = sW[(kk + 2) * 64 + v];
            float w3 = sW[(kk + 3) * 64 + v];
            #pragma unroll
            for (int r = 0; r < 8; ++r) {
                const float4 in4 = *(const float4*)(sIn + (rgrp * 8 + r) * 128 + kk);
                acc[r] = fmaf(in4.x, w0, fmaf(in4.y, w1, fmaf(in4.z, w2, fmaf(in4.w, w3, acc[r]))));
            }
        }
        __syncthreads();
    }

    #pragma unroll
    for (int r = 0; r < 8; ++r) {
        int rg = rbase + rgrp * 8 + r;
        if (rg >= rows) continue;
        if (mode == 0) out[(size_t)rg * 256 + v] = acc[r];
        else {
            int node = rg / 3, m = rg % 3;
            out[(size_t)node * 256 + 64 + v * 3 + m] = acc[r];
        }
    }
}

// ---------------------------------------------------------------------------
extern "C" void kernel_launch(void* const* d_in, const int* in_sizes, int n_in,
                              void* d_out, int out_size) {
    const float* nf    = (const float*)d_in[0];
    const float* attrs = (const float*)d_in[1];
    const float* ea    = (const float*)d_in[2];
    const float* ee    = (const float*)d_in[3];
    const int*   ei    = (const int*)d_in[4];
    const float* Wl10  = (const float*)d_in[5];
    const float* Wl11  = (const float*)d_in[6];
    const float* Wfc1  = (const float*)d_in[7];
    const float* Wfc2  = (const float*)d_in[8];
    const float* Wl20  = (const float*)d_in[9];
    const float* Wl21  = (const float*)d_in[10];
    const float* Wsc0  = (const float*)d_in[11];
    const float* Wsc1  = (const float*)d_in[12];
    float* out = (float*)d_out;

    int n = in_sizes[0] / 256;
    int E = in_sizes[2] / 4;

    // CSR build; h + packed record scatter fused
    zero_deg_kernel<<<(n + 255) / 256, 256>>>(n);
    count_kernel<<<(E + 255) / 256, 256>>>(ei, E);
    scan_kernel<<<1, 1024>>>(n);
    scatter_h_kernel<<<(E + 255) / 256, 256>>>(ei, ee, ea, Wfc1, E);

    // Node pre (y0, y1)
    int pre_nb0 = (n + 31) / 32, pre_nb1 = (3 * n + 31) / 32;
    pre_gemm_kernel<<<pre_nb0 + pre_nb1, 256>>>(nf, Wl10, Wl11, n, pre_nb0);

    // Aggregation (packed record stream)
    agg_kernel<<<n, 256>>>(Wfc2, E, n);

    // Node post (o0, o1)
    int post_nb0 = (n + 31) / 32, post_nb1 = (3 * n + 31) / 32;
    post_gemm_kernel<<<post_nb0 + post_nb1, 256>>>(nf, attrs, Wl20, Wl21, Wsc0, Wsc1, out, n, post_nb0);
}